// round 2
// baseline (speedup 1.0000x reference)
#include <cuda_runtime.h>

namespace {
constexpr int B   = 8;
constexpr int H   = 97;
constexpr int W   = 97;
constexpr int C   = 512;
constexpr int CIN = 64;
constexpr int P   = H * W;     // 9409
constexpr int S   = H + W;     // 194
constexpr float NEG_INF = -1000000000.0f;
}

// ---------------- scratch (device globals: no allocation allowed) ----------
__device__ float g_xT[B * P * C];    // x, position-major  (B, P, C)
__device__ float g_yT[B * P * C];    // ping-pong output
__device__ float g_vT[B * P * C];    // v, position-major
__device__ float g_q [B * P * CIN];
__device__ float g_k [B * P * CIN];
__device__ float g_s [B * P * S];    // scores / attention (B, P, 194)

// ---------------- transpose (B,C,P) <-> (B,P,C) ----------------------------
__global__ void transpose_in(const float* __restrict__ src, float* __restrict__ dst) {
    __shared__ float t[32][33];
    int b  = blockIdx.z;
    int n0 = blockIdx.x * 32, c0 = blockIdx.y * 32;
    const float* sp = src + (long)b * C * P;
    float*       dp = dst + (long)b * P * C;
    #pragma unroll
    for (int i = threadIdx.y; i < 32; i += 8) {
        int n = n0 + threadIdx.x;
        if (n < P) t[i][threadIdx.x] = sp[(long)(c0 + i) * P + n];
    }
    __syncthreads();
    #pragma unroll
    for (int i = threadIdx.y; i < 32; i += 8) {
        int n = n0 + i;
        if (n < P) dp[(long)n * C + c0 + threadIdx.x] = t[threadIdx.x][i];
    }
}

__global__ void transpose_out(const float* __restrict__ src, float* __restrict__ dst) {
    __shared__ float t[32][33];
    int b  = blockIdx.z;
    int n0 = blockIdx.x * 32, c0 = blockIdx.y * 32;
    const float* sp = src + (long)b * P * C;
    float*       dp = dst + (long)b * C * P;
    #pragma unroll
    for (int i = threadIdx.y; i < 32; i += 8) {
        int n = n0 + i;
        if (n < P) t[i][threadIdx.x] = sp[(long)n * C + c0 + threadIdx.x];
    }
    __syncthreads();
    #pragma unroll
    for (int i = threadIdx.y; i < 32; i += 8) {
        int n = n0 + threadIdx.x;
        if (n < P) dp[(long)(c0 + i) * P + n] = t[threadIdx.x][i];
    }
}

// ---------------- projection GEMM: C[n,m] = sum_k A[n,k] * Wt[m,k] + bias[m]
// A: (Md x Kd) row-major, batched.  Wt: (Nd x Kd) row-major (shared weights).
template<int BM, int BN, int BK, int TM, int TN>
__global__ __launch_bounds__((BM/TM)*(BN/TN))
void proj_gemm(const float* __restrict__ A, const float* __restrict__ Wt,
               const float* __restrict__ bias, float* __restrict__ Cg,
               int Md, int Nd, int Kd) {
    constexpr int THREADS = (BM / TM) * (BN / TN);
    __shared__ __align__(16) float As[BK][BM];
    __shared__ __align__(16) float Bs[BK][BN];
    int b = blockIdx.z;
    const float* Ab = A  + (long)b * Md * Kd;
    float*       Cb = Cg + (long)b * Md * Nd;
    int row0 = blockIdx.y * BM, col0 = blockIdx.x * BN;
    int tid = threadIdx.x;
    int tx = tid % (BN / TN), ty = tid / (BN / TN);

    float acc[TM][TN];
    #pragma unroll
    for (int i = 0; i < TM; i++)
        #pragma unroll
        for (int j = 0; j < TN; j++) acc[i][j] = 0.f;

    for (int k0 = 0; k0 < Kd; k0 += BK) {
        #pragma unroll
        for (int idx = tid * 4; idx < BM * BK; idx += THREADS * 4) {
            int m = idx / BK, kk = idx % BK;
            int gmr = row0 + m;
            float4 t = (gmr < Md) ? *(const float4*)&Ab[(long)gmr * Kd + k0 + kk]
                                  : make_float4(0.f, 0.f, 0.f, 0.f);
            As[kk + 0][m] = t.x; As[kk + 1][m] = t.y;
            As[kk + 2][m] = t.z; As[kk + 3][m] = t.w;
        }
        #pragma unroll
        for (int idx = tid * 4; idx < BN * BK; idx += THREADS * 4) {
            int nn = idx / BK, kk = idx % BK;
            float4 t = *(const float4*)&Wt[(long)(col0 + nn) * Kd + k0 + kk];
            Bs[kk + 0][nn] = t.x; Bs[kk + 1][nn] = t.y;
            Bs[kk + 2][nn] = t.z; Bs[kk + 3][nn] = t.w;
        }
        __syncthreads();
        #pragma unroll
        for (int kk = 0; kk < BK; kk++) {
            float ar[TM], br[TN];
            #pragma unroll
            for (int i4 = 0; i4 < TM; i4 += 4) {
                float4 t = *(const float4*)&As[kk][ty * TM + i4];
                ar[i4] = t.x; ar[i4 + 1] = t.y; ar[i4 + 2] = t.z; ar[i4 + 3] = t.w;
            }
            #pragma unroll
            for (int j4 = 0; j4 < TN; j4 += 4) {
                float4 t = *(const float4*)&Bs[kk][tx * TN + j4];
                br[j4] = t.x; br[j4 + 1] = t.y; br[j4 + 2] = t.z; br[j4 + 3] = t.w;
            }
            #pragma unroll
            for (int i = 0; i < TM; i++)
                #pragma unroll
                for (int j = 0; j < TN; j++)
                    acc[i][j] += ar[i] * br[j];
        }
        __syncthreads();
    }

    float bsv[TN];
    #pragma unroll
    for (int j = 0; j < TN; j++) bsv[j] = bias[col0 + tx * TN + j];
    #pragma unroll
    for (int i = 0; i < TM; i++) {
        int gmr = row0 + ty * TM + i;
        if (gmr >= Md) continue;
        #pragma unroll
        for (int j4 = 0; j4 < TN; j4 += 4) {
            float4 o;
            o.x = acc[i][j4 + 0] + bsv[j4 + 0];
            o.y = acc[i][j4 + 1] + bsv[j4 + 1];
            o.z = acc[i][j4 + 2] + bsv[j4 + 2];
            o.w = acc[i][j4 + 3] + bsv[j4 + 3];
            *(float4*)&Cb[(long)gmr * Nd + col0 + tx * TN + j4] = o;
        }
    }
}

// ---------------- scores: per line (column if COLMODE else row) ------------
// COLMODE=true  (eH): fixed w=yy, query h, key g, n = r*W + yy, diag mask.
// COLMODE=false (eW): fixed h=yy, query w, key u, n = yy*W + r, col offset 97.
template<bool COLMODE>
__global__ __launch_bounds__(256)
void score_kernel(const float* __restrict__ q, const float* __restrict__ k,
                  float* __restrict__ s) {
    __shared__ __align__(16) float Qs[64][64];
    __shared__ __align__(16) float Kt[64][97];   // transposed keys: Kt[c][g]
    int b = blockIdx.z, yy = blockIdx.y;
    int h0 = blockIdx.x * 49;
    int hcnt = (h0 == 0) ? 49 : 48;
    long base = (long)b * P + (COLMODE ? yy : yy * W);
    int rstride = COLMODE ? W : 1;
    const float* qb = q + base * CIN;
    const float* kb = k + base * CIN;
    int tid = threadIdx.x;

    for (int idx = tid; idx < hcnt * 64; idx += 256) {
        int r = idx >> 6, c = idx & 63;
        Qs[r][c] = qb[(long)(h0 + r) * rstride * CIN + c];
    }
    for (int idx = tid; idx < 97 * 64; idx += 256) {
        int g = idx >> 6, c = idx & 63;
        Kt[c][g] = kb[(long)g * rstride * CIN + c];
    }
    __syncthreads();

    int tx = tid & 15, ty = tid >> 4;
    int gi[7];
    #pragma unroll
    for (int j = 0; j < 7; j++) { int g = tx + 16 * j; gi[j] = g < 97 ? g : 96; }
    float acc[4][7];
    #pragma unroll
    for (int i = 0; i < 4; i++)
        #pragma unroll
        for (int j = 0; j < 7; j++) acc[i][j] = 0.f;

    #pragma unroll 8
    for (int c = 0; c < 64; c++) {
        float aq[4], kv[7];
        #pragma unroll
        for (int i = 0; i < 4; i++) aq[i] = Qs[ty + 16 * i][c];
        #pragma unroll
        for (int j = 0; j < 7; j++) kv[j] = Kt[c][gi[j]];
        #pragma unroll
        for (int i = 0; i < 4; i++)
            #pragma unroll
            for (int j = 0; j < 7; j++)
                acc[i][j] += aq[i] * kv[j];
    }

    #pragma unroll
    for (int i = 0; i < 4; i++) {
        int r = ty + 16 * i;
        if (r >= hcnt) continue;
        int rg = h0 + r;
        long n = COLMODE ? (long)rg * W + yy : (long)yy * W + rg;
        float* out = s + ((long)b * P + n) * S + (COLMODE ? 0 : 97);
        #pragma unroll
        for (int j = 0; j < 7; j++) {
            int g = tx + 16 * j;
            if (g < 97) {
                float val = acc[i][j];
                if (COLMODE && rg == g) val += NEG_INF;
                out[g] = val;
            }
        }
    }
}

// ---------------- softmax over 194 per position (one warp per row) ---------
__global__ __launch_bounds__(256)
void softmax194(float* __restrict__ s) {
    int row  = blockIdx.x * 8 + (threadIdx.x >> 5);   // grid = P blocks -> B*P rows
    int lane = threadIdx.x & 31;
    float* r = s + (long)row * S;
    float v[7];
    float m = -3.0e38f;
    #pragma unroll
    for (int t = 0; t < 7; t++) {
        int idx = lane + 32 * t;
        v[t] = (idx < S) ? r[idx] : -3.0e38f;
        m = fmaxf(m, v[t]);
    }
    #pragma unroll
    for (int o = 16; o > 0; o >>= 1) m = fmaxf(m, __shfl_xor_sync(0xffffffffu, m, o));
    float sum = 0.f;
    #pragma unroll
    for (int t = 0; t < 7; t++) { v[t] = __expf(v[t] - m); sum += v[t]; }
    #pragma unroll
    for (int o = 16; o > 0; o >>= 1) sum += __shfl_xor_sync(0xffffffffu, sum, o);
    float inv = 1.0f / sum;
    #pragma unroll
    for (int t = 0; t < 7; t++) {
        int idx = lane + 32 * t;
        if (idx < S) r[idx] = v[t] * inv;
    }
}

// ---------------- apply: out(97 x 128c-chunk) = A(97x97) @ V(97 x 128c) ----
// COLMODE=true  (outH): fixed w=yy, rows h, keys g (n=g*W+yy); writes Y.
// COLMODE=false (outW): fixed h=yy, rows w, keys u (contiguous);
//                       final: Y = gamma*(Yprev + outW) + X.
template<bool COLMODE>
__global__ __launch_bounds__(256)
void apply_kernel(const float* __restrict__ s, const float* __restrict__ v,
                  float* __restrict__ y, const float* __restrict__ x,
                  const float* __restrict__ gamma) {
    __shared__ __align__(16) float As[97][97];
    __shared__ __align__(16) float Vs[16][128];
    int b = blockIdx.z, yy = blockIdx.y, c0 = blockIdx.x * 128;
    long nb = (long)b * P + (COLMODE ? yy : yy * W);
    int rstride = COLMODE ? W : 1;
    const float* sb = s + nb * S + (COLMODE ? 0 : 97);
    const float* vb = v + nb * C + c0;
    float*       yb = y + nb * C + c0;
    const float* xb = x + nb * C + c0;
    int tid = threadIdx.x;

    for (int idx = tid; idx < 97 * 97; idx += 256) {
        int r = idx / 97, g = idx % 97;
        As[r][g] = sb[(long)r * rstride * S + g];
    }
    __syncthreads();

    int tx = tid & 15, ty = tid >> 4;
    int ri[7];
    #pragma unroll
    for (int i = 0; i < 7; i++) { int r = ty + 16 * i; ri[i] = r < 97 ? r : 96; }
    float acc[7][8];
    #pragma unroll
    for (int i = 0; i < 7; i++)
        #pragma unroll
        for (int j = 0; j < 8; j++) acc[i][j] = 0.f;

    for (int g0 = 0; g0 < 97; g0 += 16) {
        int gmax = 97 - g0; if (gmax > 16) gmax = 16;
        __syncthreads();
        for (int idx = tid; idx < gmax * 128; idx += 256) {
            int g = idx >> 7, cc = idx & 127;
            Vs[g][cc] = vb[(long)(g0 + g) * rstride * C + cc];
        }
        __syncthreads();
        for (int g = 0; g < gmax; g++) {
            float a[7];
            #pragma unroll
            for (int i = 0; i < 7; i++) a[i] = As[ri[i]][g0 + g];
            float4 v0 = *(const float4*)&Vs[g][tx * 8];
            float4 v1 = *(const float4*)&Vs[g][tx * 8 + 4];
            #pragma unroll
            for (int i = 0; i < 7; i++) {
                acc[i][0] += a[i] * v0.x; acc[i][1] += a[i] * v0.y;
                acc[i][2] += a[i] * v0.z; acc[i][3] += a[i] * v0.w;
                acc[i][4] += a[i] * v1.x; acc[i][5] += a[i] * v1.y;
                acc[i][6] += a[i] * v1.z; acc[i][7] += a[i] * v1.w;
            }
        }
    }

    float gmv = 0.f;
    if (!COLMODE) gmv = __ldg(gamma);
    #pragma unroll
    for (int i = 0; i < 7; i++) {
        int r = ty + 16 * i;
        if (r >= 97) continue;
        long off = (long)r * rstride * C + tx * 8;
        if (COLMODE) {
            float4 o0, o1;
            o0.x = acc[i][0]; o0.y = acc[i][1]; o0.z = acc[i][2]; o0.w = acc[i][3];
            o1.x = acc[i][4]; o1.y = acc[i][5]; o1.z = acc[i][6]; o1.w = acc[i][7];
            *(float4*)&yb[off] = o0;
            *(float4*)&yb[off + 4] = o1;
        } else {
            float4 p0 = *(const float4*)&yb[off];
            float4 p1 = *(const float4*)&yb[off + 4];
            float4 x0 = *(const float4*)&xb[off];
            float4 x1 = *(const float4*)&xb[off + 4];
            float4 o0, o1;
            o0.x = gmv * (p0.x + acc[i][0]) + x0.x;
            o0.y = gmv * (p0.y + acc[i][1]) + x0.y;
            o0.z = gmv * (p0.z + acc[i][2]) + x0.z;
            o0.w = gmv * (p0.w + acc[i][3]) + x0.w;
            o1.x = gmv * (p1.x + acc[i][4]) + x1.x;
            o1.y = gmv * (p1.y + acc[i][5]) + x1.y;
            o1.z = gmv * (p1.z + acc[i][6]) + x1.z;
            o1.w = gmv * (p1.w + acc[i][7]) + x1.w;
            *(float4*)&yb[off] = o0;
            *(float4*)&yb[off + 4] = o1;
        }
    }
}

// ---------------- launch ---------------------------------------------------
extern "C" void kernel_launch(void* const* d_in, const int* in_sizes, int n_in,
                              void* d_out, int out_size) {
    const float* x     = (const float*)d_in[0];
    const float* Wq    = (const float*)d_in[1];
    const float* bq    = (const float*)d_in[2];
    const float* Wk    = (const float*)d_in[3];
    const float* bk    = (const float*)d_in[4];
    const float* Wv    = (const float*)d_in[5];
    const float* bv    = (const float*)d_in[6];
    const float* gamma = (const float*)d_in[7];
    float* out = (float*)d_out;

    float *xT, *yT, *vT, *qp, *kp, *sp;
    cudaGetSymbolAddress((void**)&xT, g_xT);
    cudaGetSymbolAddress((void**)&yT, g_yT);
    cudaGetSymbolAddress((void**)&vT, g_vT);
    cudaGetSymbolAddress((void**)&qp, g_q);
    cudaGetSymbolAddress((void**)&kp, g_k);
    cudaGetSymbolAddress((void**)&sp, g_s);

    dim3 tgrid((P + 31) / 32, C / 32, B), tthr(32, 8);
    transpose_in<<<tgrid, tthr>>>(x, xT);

    for (int it = 0; it < 2; it++) {
        const float* X = it ? yT : xT;
        float*       Y = it ? xT : yT;
        proj_gemm<128, 64, 8, 8, 4><<<dim3(1, (P + 127) / 128, B), 256>>>(X, Wq, bq, qp, P, CIN, C);
        proj_gemm<128, 64, 8, 8, 4><<<dim3(1, (P + 127) / 128, B), 256>>>(X, Wk, bk, kp, P, CIN, C);
        proj_gemm<128, 128, 8, 8, 8><<<dim3(C / 128, (P + 127) / 128, B), 256>>>(X, Wv, bv, vT, P, C, C);
        score_kernel<true ><<<dim3(2, W, B), 256>>>(qp, kp, sp);
        score_kernel<false><<<dim3(2, H, B), 256>>>(qp, kp, sp);
        softmax194<<<P, 256>>>(sp);
        apply_kernel<true ><<<dim3(4, W, B), 256>>>(sp, vT, Y, X, gamma);
        apply_kernel<false><<<dim3(4, H, B), 256>>>(sp, vT, Y, X, gamma);
    }

    transpose_out<<<tgrid, tthr>>>(xT, out);   // iter-1 output lands in g_xT
}

// round 4
// speedup vs baseline: 1.3308x; 1.3308x over previous
#include <cuda_runtime.h>
#include <cuda_bf16.h>
#include <cstdint>

namespace {
constexpr int B   = 8;
constexpr int H   = 97;
constexpr int W   = 97;
constexpr int C   = 512;
constexpr int P   = H * W;        // 9409
constexpr int S   = H + W;        // 194
constexpr int BP  = B * P;        // 75272
constexpr int KS  = 3 * C;        // 1536 split-K
constexpr int MBLK = (BP + 127) / 128;   // 589
constexpr float NEG_INF = -1000000000.0f;
}

// ---------------- scratch ---------------------------------------------------
__device__ float g_xT[BP * C];
__device__ float g_yT[BP * C];
__device__ float g_vT[BP * C];
__device__ float g_qk[BP * 128];            // q (0..63) | k (64..127)
__device__ float g_s [BP * S];
__device__ __nv_bfloat16 g_xs  [(long)BP * KS];   // split x: [hi, lo, hi]
__device__ __nv_bfloat16 g_wsv [C * KS];          // split Wv: [hi, hi, lo]
__device__ __nv_bfloat16 g_wsqk[128 * KS];        // split Wq|Wk
__device__ float g_bqk[128];

__device__ __forceinline__ uint32_t smem_u32(const void* p) {
    uint32_t a;
    asm("{ .reg .u64 t; cvta.to.shared.u64 t, %1; cvt.u32.u64 %0, t; }" : "=r"(a) : "l"(p));
    return a;
}

// ---------------- transpose (B,C,P) <-> (B,P,C) -----------------------------
__global__ void transpose_in(const float* __restrict__ src, float* __restrict__ dst) {
    __shared__ float t[32][33];
    int b = blockIdx.z, n0 = blockIdx.x * 32, c0 = blockIdx.y * 32;
    const float* sp = src + (long)b * C * P;
    float*       dp = dst + (long)b * P * C;
    for (int i = threadIdx.y; i < 32; i += 8) {
        int n = n0 + threadIdx.x;
        if (n < P) t[i][threadIdx.x] = sp[(long)(c0 + i) * P + n];
    }
    __syncthreads();
    for (int i = threadIdx.y; i < 32; i += 8) {
        int n = n0 + i;
        if (n < P) dp[(long)n * C + c0 + threadIdx.x] = t[threadIdx.x][i];
    }
}
__global__ void transpose_out(const float* __restrict__ src, float* __restrict__ dst) {
    __shared__ float t[32][33];
    int b = blockIdx.z, n0 = blockIdx.x * 32, c0 = blockIdx.y * 32;
    const float* sp = src + (long)b * P * C;
    float*       dp = dst + (long)b * C * P;
    for (int i = threadIdx.y; i < 32; i += 8) {
        int n = n0 + i;
        if (n < P) t[i][threadIdx.x] = sp[(long)n * C + c0 + threadIdx.x];
    }
    __syncthreads();
    for (int i = threadIdx.y; i < 32; i += 8) {
        int n = n0 + threadIdx.x;
        if (n < P) dp[(long)(c0 + i) * P + n] = t[threadIdx.x][i];
    }
}

// ---------------- split conversion -----------------------------------------
__global__ __launch_bounds__(256) void split_x(const float* __restrict__ X, __nv_bfloat16* __restrict__ Xs) {
    long i = (long)blockIdx.x * 256 + threadIdx.x;     // one 4-float granule
    if (i >= (long)BP * 128) return;
    long m = i >> 7; int c4 = (int)(i & 127) * 4;
    float4 x = *(const float4*)&X[m * C + c4];
    __nv_bfloat16 h0 = __float2bfloat16(x.x), h1 = __float2bfloat16(x.y);
    __nv_bfloat16 h2 = __float2bfloat16(x.z), h3 = __float2bfloat16(x.w);
    __nv_bfloat16 l0 = __float2bfloat16(x.x - __bfloat162float(h0));
    __nv_bfloat16 l1 = __float2bfloat16(x.y - __bfloat162float(h1));
    __nv_bfloat16 l2 = __float2bfloat16(x.z - __bfloat162float(h2));
    __nv_bfloat16 l3 = __float2bfloat16(x.w - __bfloat162float(h3));
    __nv_bfloat16* row = Xs + m * KS;
    __nv_bfloat162 H01; H01.x = h0; H01.y = h1;
    __nv_bfloat162 H23; H23.x = h2; H23.y = h3;
    __nv_bfloat162 L01; L01.x = l0; L01.y = l1;
    __nv_bfloat162 L23; L23.x = l2; L23.y = l3;
    *(__nv_bfloat162*)&row[c4]            = H01; *(__nv_bfloat162*)&row[c4 + 2]        = H23;
    *(__nv_bfloat162*)&row[C + c4]        = L01; *(__nv_bfloat162*)&row[C + c4 + 2]    = L23;
    *(__nv_bfloat162*)&row[2*C + c4]      = H01; *(__nv_bfloat162*)&row[2*C + c4 + 2]  = H23;
}

// weights: rows 0..511 -> Wv, rows 512..639 -> Wq|Wk. B sections: [hi, hi, lo]
__global__ __launch_bounds__(256) void prep_w(const float* __restrict__ Wq, const float* __restrict__ Wk,
                                              const float* __restrict__ Wv, const float* __restrict__ bq,
                                              const float* __restrict__ bk) {
    int i = blockIdx.x * 256 + threadIdx.x;
    if (blockIdx.x == 0 && threadIdx.x < 128)
        g_bqk[threadIdx.x] = threadIdx.x < 64 ? bq[threadIdx.x] : bk[threadIdx.x - 64];
    if (i >= 640 * 128) return;
    int r = i >> 7, c4 = (i & 127) * 4;
    const float* src; __nv_bfloat16* dst;
    if (r < 512) { src = Wv + (long)r * C + c4; dst = g_wsv + (long)r * KS; }
    else {
        int rr = r - 512;
        src = (rr < 64 ? Wq + (long)rr * C : Wk + (long)(rr - 64) * C) + c4;
        dst = g_wsqk + (long)rr * KS;
    }
    float4 x = *(const float4*)src;
    __nv_bfloat16 h0 = __float2bfloat16(x.x), h1 = __float2bfloat16(x.y);
    __nv_bfloat16 h2 = __float2bfloat16(x.z), h3 = __float2bfloat16(x.w);
    __nv_bfloat16 l0 = __float2bfloat16(x.x - __bfloat162float(h0));
    __nv_bfloat16 l1 = __float2bfloat16(x.y - __bfloat162float(h1));
    __nv_bfloat16 l2 = __float2bfloat16(x.z - __bfloat162float(h2));
    __nv_bfloat16 l3 = __float2bfloat16(x.w - __bfloat162float(h3));
    __nv_bfloat162 H01; H01.x = h0; H01.y = h1;
    __nv_bfloat162 H23; H23.x = h2; H23.y = h3;
    __nv_bfloat162 L01; L01.x = l0; L01.y = l1;
    __nv_bfloat162 L23; L23.x = l2; L23.y = l3;
    *(__nv_bfloat162*)&dst[c4]           = H01; *(__nv_bfloat162*)&dst[c4 + 2]       = H23;
    *(__nv_bfloat162*)&dst[C + c4]       = H01; *(__nv_bfloat162*)&dst[C + c4 + 2]   = H23;
    *(__nv_bfloat162*)&dst[2*C + c4]     = L01; *(__nv_bfloat162*)&dst[2*C + c4 + 2] = L23;
}

// ---------------- HMMA projection GEMM: out = A(BPxKS) @ Wsp(NdxKS)^T + bias
// 128x128 CTA tile, 8 warps (2x4), warp tile 64x32 via m16n8k16 bf16 atoms.
__global__ __launch_bounds__(256)
void mma_proj(const __nv_bfloat16* __restrict__ A, const __nv_bfloat16* __restrict__ Wsp,
              const float* __restrict__ bias, float* __restrict__ out, int Nd) {
    __shared__ __align__(16) __nv_bfloat16 As[128][40];  // 32 used + 8 pad (80B rows)
    __shared__ __align__(16) __nv_bfloat16 Bs[128][40];
    int tid = threadIdx.x, lane = tid & 31, wid = tid >> 5;
    int wm = wid >> 2, wn = wid & 3;                     // 2 x 4 warp grid
    int row0 = blockIdx.x * 128, col0 = blockIdx.y * 128;

    float acc[4][4][4];
    #pragma unroll
    for (int mt = 0; mt < 4; mt++)
        #pragma unroll
        for (int nt = 0; nt < 4; nt++)
            #pragma unroll
            for (int i = 0; i < 4; i++) acc[mt][nt][i] = 0.f;

    for (int ch = 0; ch < KS / 32; ch++) {
        int k0 = ch * 32;
        #pragma unroll
        for (int j = 0; j < 2; j++) {
            int g = tid + j * 256;
            int m = g >> 2, q = g & 3;
            int gm = row0 + m;
            uint4 v = make_uint4(0u, 0u, 0u, 0u);
            if (gm < BP) v = *(const uint4*)&A[(long)gm * KS + k0 + q * 8];
            *(uint4*)&As[m][q * 8] = v;
            uint4 w = *(const uint4*)&Wsp[(long)(col0 + m) * KS + k0 + q * 8];
            *(uint4*)&Bs[m][q * 8] = w;
        }
        __syncthreads();
        #pragma unroll
        for (int ks = 0; ks < 2; ks++) {
            int kk = ks * 16;
            uint32_t afr[4][4], bfr[4][2];
            #pragma unroll
            for (int mt = 0; mt < 4; mt++) {
                uint32_t ad = smem_u32(&As[wm * 64 + mt * 16 + (lane & 15)][kk + ((lane >> 4) << 3)]);
                asm volatile("ldmatrix.sync.aligned.m8n8.x4.shared.b16 {%0,%1,%2,%3}, [%4];"
                    : "=r"(afr[mt][0]), "=r"(afr[mt][1]), "=r"(afr[mt][2]), "=r"(afr[mt][3]) : "r"(ad));
            }
            #pragma unroll
            for (int np = 0; np < 2; np++) {
                int q = lane >> 3;
                uint32_t bd = smem_u32(&Bs[wn * 32 + np * 16 + ((q >> 1) << 3) + (lane & 7)][kk + ((q & 1) << 3)]);
                uint32_t r0, r1, r2, r3;
                asm volatile("ldmatrix.sync.aligned.m8n8.x4.shared.b16 {%0,%1,%2,%3}, [%4];"
                    : "=r"(r0), "=r"(r1), "=r"(r2), "=r"(r3) : "r"(bd));
                bfr[np * 2][0] = r0; bfr[np * 2][1] = r1;
                bfr[np * 2 + 1][0] = r2; bfr[np * 2 + 1][1] = r3;
            }
            #pragma unroll
            for (int mt = 0; mt < 4; mt++)
                #pragma unroll
                for (int nt = 0; nt < 4; nt++)
                    asm volatile("mma.sync.aligned.m16n8k16.row.col.f32.bf16.bf16.f32 "
                        "{%0,%1,%2,%3}, {%4,%5,%6,%7}, {%8,%9}, {%0,%1,%2,%3};"
                        : "+f"(acc[mt][nt][0]), "+f"(acc[mt][nt][1]),
                          "+f"(acc[mt][nt][2]), "+f"(acc[mt][nt][3])
                        : "r"(afr[mt][0]), "r"(afr[mt][1]), "r"(afr[mt][2]), "r"(afr[mt][3]),
                          "r"(bfr[nt][0]), "r"(bfr[nt][1]));
        }
        __syncthreads();
    }

    #pragma unroll
    for (int mt = 0; mt < 4; mt++) {
        #pragma unroll
        for (int nt = 0; nt < 4; nt++) {
            int gn = col0 + wn * 32 + nt * 8 + 2 * (lane & 3);
            float b0 = bias[gn], b1 = bias[gn + 1];
            int gm0 = row0 + wm * 64 + mt * 16 + (lane >> 2);
            if (gm0 < BP) {
                float2 o; o.x = acc[mt][nt][0] + b0; o.y = acc[mt][nt][1] + b1;
                *(float2*)&out[(long)gm0 * Nd + gn] = o;
            }
            int gm1 = gm0 + 8;
            if (gm1 < BP) {
                float2 o; o.x = acc[mt][nt][2] + b0; o.y = acc[mt][nt][3] + b1;
                *(float2*)&out[(long)gm1 * Nd + gn] = o;
            }
        }
    }
}

// ---------------- scores (q/k packed, stride 128) ---------------------------
template<bool COLMODE>
__global__ __launch_bounds__(256)
void score_kernel(const float* __restrict__ qk, float* __restrict__ s) {
    __shared__ __align__(16) float Qs[64][64];
    __shared__ __align__(16) float Kt[64][97];
    int b = blockIdx.z, yy = blockIdx.y;
    int h0 = blockIdx.x * 49;
    int hcnt = (h0 == 0) ? 49 : 48;
    long base = (long)b * P + (COLMODE ? yy : yy * W);
    int rstride = COLMODE ? W : 1;
    const float* qb = qk + base * 128;
    const float* kb = qk + base * 128 + 64;
    int tid = threadIdx.x;

    for (int idx = tid; idx < hcnt * 64; idx += 256) {
        int r = idx >> 6, c = idx & 63;
        Qs[r][c] = qb[(long)(h0 + r) * rstride * 128 + c];
    }
    for (int idx = tid; idx < 97 * 64; idx += 256) {
        int g = idx >> 6, c = idx & 63;
        Kt[c][g] = kb[(long)g * rstride * 128 + c];
    }
    __syncthreads();

    int tx = tid & 15, ty = tid >> 4;
    int gi[7];
    #pragma unroll
    for (int j = 0; j < 7; j++) { int g = tx + 16 * j; gi[j] = g < 97 ? g : 96; }
    float acc[4][7];
    #pragma unroll
    for (int i = 0; i < 4; i++)
        #pragma unroll
        for (int j = 0; j < 7; j++) acc[i][j] = 0.f;

    #pragma unroll 8
    for (int c = 0; c < 64; c++) {
        float aq[4], kv[7];
        #pragma unroll
        for (int i = 0; i < 4; i++) aq[i] = Qs[ty + 16 * i][c];
        #pragma unroll
        for (int j = 0; j < 7; j++) kv[j] = Kt[c][gi[j]];
        #pragma unroll
        for (int i = 0; i < 4; i++)
            #pragma unroll
            for (int j = 0; j < 7; j++)
                acc[i][j] += aq[i] * kv[j];
    }

    #pragma unroll
    for (int i = 0; i < 4; i++) {
        int r = ty + 16 * i;
        if (r >= hcnt) continue;
        int rg = h0 + r;
        long n = COLMODE ? (long)rg * W + yy : (long)yy * W + rg;
        float* outp = s + ((long)b * P + n) * S + (COLMODE ? 0 : 97);
        #pragma unroll
        for (int j = 0; j < 7; j++) {
            int g = tx + 16 * j;
            if (g < 97) {
                float val = acc[i][j];
                if (COLMODE && rg == g) val += NEG_INF;
                outp[g] = val;
            }
        }
    }
}

// ---------------- softmax ----------------------------------------------------
__global__ __launch_bounds__(256)
void softmax194(float* __restrict__ s) {
    int row  = blockIdx.x * 8 + (threadIdx.x >> 5);
    int lane = threadIdx.x & 31;
    float* r = s + (long)row * S;
    float v[7];
    float m = -3.0e38f;
    #pragma unroll
    for (int t = 0; t < 7; t++) {
        int idx = lane + 32 * t;
        v[t] = (idx < S) ? r[idx] : -3.0e38f;
        m = fmaxf(m, v[t]);
    }
    #pragma unroll
    for (int o = 16; o > 0; o >>= 1) m = fmaxf(m, __shfl_xor_sync(0xffffffffu, m, o));
    float sum = 0.f;
    #pragma unroll
    for (int t = 0; t < 7; t++) { v[t] = __expf(v[t] - m); sum += v[t]; }
    #pragma unroll
    for (int o = 16; o > 0; o >>= 1) sum += __shfl_xor_sync(0xffffffffu, sum, o);
    float inv = 1.0f / sum;
    #pragma unroll
    for (int t = 0; t < 7; t++) {
        int idx = lane + 32 * t;
        if (idx < S) r[idx] = v[t] * inv;
    }
}

// ---------------- apply -------------------------------------------------------
template<bool COLMODE>
__global__ __launch_bounds__(256)
void apply_kernel(const float* __restrict__ s, const float* __restrict__ v,
                  float* __restrict__ y, const float* __restrict__ x,
                  const float* __restrict__ gamma) {
    __shared__ __align__(16) float As[97][97];
    __shared__ __align__(16) float Vs[16][128];
    int b = blockIdx.z, yy = blockIdx.y, c0 = blockIdx.x * 128;
    long nb = (long)b * P + (COLMODE ? yy : yy * W);
    int rstride = COLMODE ? W : 1;
    const float* sb = s + nb * S + (COLMODE ? 0 : 97);
    const float* vb = v + nb * C + c0;
    float*       yb = y + nb * C + c0;
    const float* xb = x + nb * C + c0;
    int tid = threadIdx.x;

    for (int idx = tid; idx < 97 * 97; idx += 256) {
        int r = idx / 97, g = idx % 97;
        As[r][g] = sb[(long)r * rstride * S + g];
    }
    __syncthreads();

    int tx = tid & 15, ty = tid >> 4;
    int ri[7];
    #pragma unroll
    for (int i = 0; i < 7; i++) { int r = ty + 16 * i; ri[i] = r < 97 ? r : 96; }
    float acc[7][8];
    #pragma unroll
    for (int i = 0; i < 7; i++)
        #pragma unroll
        for (int j = 0; j < 8; j++) acc[i][j] = 0.f;

    for (int g0 = 0; g0 < 97; g0 += 16) {
        int gmax = 97 - g0; if (gmax > 16) gmax = 16;
        __syncthreads();
        for (int idx = tid; idx < gmax * 128; idx += 256) {
            int g = idx >> 7, cc = idx & 127;
            Vs[g][cc] = vb[(long)(g0 + g) * rstride * C + cc];
        }
        __syncthreads();
        for (int g = 0; g < gmax; g++) {
            float a[7];
            #pragma unroll
            for (int i = 0; i < 7; i++) a[i] = As[ri[i]][g0 + g];
            float4 v0 = *(const float4*)&Vs[g][tx * 8];
            float4 v1 = *(const float4*)&Vs[g][tx * 8 + 4];
            #pragma unroll
            for (int i = 0; i < 7; i++) {
                acc[i][0] += a[i] * v0.x; acc[i][1] += a[i] * v0.y;
                acc[i][2] += a[i] * v0.z; acc[i][3] += a[i] * v0.w;
                acc[i][4] += a[i] * v1.x; acc[i][5] += a[i] * v1.y;
                acc[i][6] += a[i] * v1.z; acc[i][7] += a[i] * v1.w;
            }
        }
    }

    float gmv = 0.f;
    if (!COLMODE) gmv = __ldg(gamma);
    #pragma unroll
    for (int i = 0; i < 7; i++) {
        int r = ty + 16 * i;
        if (r >= 97) continue;
        long off = (long)r * rstride * C + tx * 8;
        if (COLMODE) {
            float4 o0, o1;
            o0.x = acc[i][0]; o0.y = acc[i][1]; o0.z = acc[i][2]; o0.w = acc[i][3];
            o1.x = acc[i][4]; o1.y = acc[i][5]; o1.z = acc[i][6]; o1.w = acc[i][7];
            *(float4*)&yb[off] = o0;
            *(float4*)&yb[off + 4] = o1;
        } else {
            float4 p0 = *(const float4*)&yb[off];
            float4 p1 = *(const float4*)&yb[off + 4];
            float4 x0 = *(const float4*)&xb[off];
            float4 x1 = *(const float4*)&xb[off + 4];
            float4 o0, o1;
            o0.x = gmv * (p0.x + acc[i][0]) + x0.x;
            o0.y = gmv * (p0.y + acc[i][1]) + x0.y;
            o0.z = gmv * (p0.z + acc[i][2]) + x0.z;
            o0.w = gmv * (p0.w + acc[i][3]) + x0.w;
            o1.x = gmv * (p1.x + acc[i][4]) + x1.x;
            o1.y = gmv * (p1.y + acc[i][5]) + x1.y;
            o1.z = gmv * (p1.z + acc[i][6]) + x1.z;
            o1.w = gmv * (p1.w + acc[i][7]) + x1.w;
            *(float4*)&yb[off] = o0;
            *(float4*)&yb[off + 4] = o1;
        }
    }
}

// ---------------- launch -----------------------------------------------------
extern "C" void kernel_launch(void* const* d_in, const int* in_sizes, int n_in,
                              void* d_out, int out_size) {
    const float* x     = (const float*)d_in[0];
    const float* Wq    = (const float*)d_in[1];
    const float* bq    = (const float*)d_in[2];
    const float* Wk    = (const float*)d_in[3];
    const float* bk    = (const float*)d_in[4];
    const float* Wv    = (const float*)d_in[5];
    const float* bv    = (const float*)d_in[6];
    const float* gamma = (const float*)d_in[7];
    float* out = (float*)d_out;

    float *xT, *yT, *vT, *qk, *sp, *bqk;
    __nv_bfloat16 *xs, *wsv, *wsqk;
    cudaGetSymbolAddress((void**)&xT,  g_xT);
    cudaGetSymbolAddress((void**)&yT,  g_yT);
    cudaGetSymbolAddress((void**)&vT,  g_vT);
    cudaGetSymbolAddress((void**)&qk,  g_qk);
    cudaGetSymbolAddress((void**)&sp,  g_s);
    cudaGetSymbolAddress((void**)&xs,   g_xs);
    cudaGetSymbolAddress((void**)&wsv,  g_wsv);
    cudaGetSymbolAddress((void**)&wsqk, g_wsqk);
    cudaGetSymbolAddress((void**)&bqk,  g_bqk);

    dim3 tgrid((P + 31) / 32, C / 32, B), tthr(32, 8);
    transpose_in<<<tgrid, tthr>>>(x, xT);
    prep_w<<<320, 256>>>(Wq, Wk, Wv, bq, bk);

    for (int it = 0; it < 2; it++) {
        const float* X = it ? yT : xT;
        float*       Y = it ? xT : yT;
        split_x<<<(int)(((long)BP * 128 + 255) / 256), 256>>>(X, xs);
        mma_proj<<<dim3(MBLK, 1), 256>>>(xs, wsqk, bqk, qk, 128);
        mma_proj<<<dim3(MBLK, 4), 256>>>(xs, wsv, bv, vT, 512);
        score_kernel<true ><<<dim3(2, W, B), 256>>>(qk, sp);
        score_kernel<false><<<dim3(2, H, B), 256>>>(qk, sp);
        softmax194<<<P, 256>>>(sp);
        apply_kernel<true ><<<dim3(4, W, B), 256>>>(sp, vT, Y, X, gamma);
        apply_kernel<false><<<dim3(4, H, B), 256>>>(sp, vT, Y, X, gamma);
    }

    transpose_out<<<tgrid, tthr>>>(xT, out);
}